// round 15
// baseline (speedup 1.0000x reference)
#include <cuda_runtime.h>
#include <cuda_fp16.h>
#include <math.h>
#include <stdint.h>

#define EMB   1024
#define SEQ   1024
#define BATCH 8
#define NH    16
#define HD    64
#define TOK   (BATCH*SEQ)   // 8192

// Scratch — fp16 everywhere
__device__ __half g_qkv16[(size_t)TOK * EMB];
__device__ __half g_win16[(size_t)3 * EMB * EMB];
__device__ __half g_wout16[(size_t)EMB * EMB];
__device__ __half g_proj[(size_t)TOK * 3 * EMB];
__device__ __half g_ctx[(size_t)TOK * EMB];

// ---------------------------------------------------------------------------
__device__ __forceinline__ float ex2(float x) {
    float y; asm("ex2.approx.ftz.f32 %0, %1;" : "=f"(y) : "f"(x)); return y;
}
__device__ __forceinline__ uint32_t s2u(const void* p) {
    return (uint32_t)__cvta_generic_to_shared(p);
}
__device__ __forceinline__ void mma_f16(float c[4], const unsigned a[4],
                                        unsigned b0, unsigned b1) {
    asm volatile(
        "mma.sync.aligned.m16n8k16.row.col.f32.f16.f16.f32 "
        "{%0,%1,%2,%3}, {%4,%5,%6,%7}, {%8,%9}, {%0,%1,%2,%3};"
        : "+f"(c[0]), "+f"(c[1]), "+f"(c[2]), "+f"(c[3])
        : "r"(a[0]), "r"(a[1]), "r"(a[2]), "r"(a[3]), "r"(b0), "r"(b1));
}
__device__ __forceinline__ void ldsm_x4(unsigned r[4], uint32_t addr) {
    asm volatile("ldmatrix.sync.aligned.m8n8.x4.shared.b16 {%0,%1,%2,%3}, [%4];"
        : "=r"(r[0]), "=r"(r[1]), "=r"(r[2]), "=r"(r[3]) : "r"(addr));
}
__device__ __forceinline__ void ldsm_x4_t(unsigned r[4], uint32_t addr) {
    asm volatile("ldmatrix.sync.aligned.m8n8.x4.trans.shared.b16 {%0,%1,%2,%3}, [%4];"
        : "=r"(r[0]), "=r"(r[1]), "=r"(r[2]), "=r"(r[3]) : "r"(addr));
}
__device__ __forceinline__ unsigned packh2(float a, float b) {
    __half2 h = __floats2half2_rn(a, b);
    return *(unsigned*)&h;
}
__device__ __forceinline__ void cp16(uint32_t dst, const void* src) {
    asm volatile("cp.async.cg.shared.global [%0], [%1], 16;" :: "r"(dst), "l"(src));
}
#define CP_COMMIT() asm volatile("cp.async.commit_group;")
#define CP_WAIT(n)  asm volatile("cp.async.wait_group %0;" :: "n"(n))

// ---------------------------------------------------------------------------
__global__ __launch_bounds__(256) void to_half(const float4* __restrict__ src,
                                               uint2* __restrict__ dst, int n4)
{
    int i = blockIdx.x * blockDim.x + threadIdx.x;
    if (i < n4) {
        float4 v = src[i];
        uint2 o = { packh2(v.x, v.y), packh2(v.z, v.w) };
        dst[i] = o;
    }
}

// ---------------------------------------------------------------------------
// GEMM: CTA 128x128, 256 threads, 8 warps (2x4), warp tile 64x32, BK=32.
// 3-stage cp.async pipeline; small warp state -> 2 CTAs/SM without reg caps.
// ---------------------------------------------------------------------------
#define BK  32
#define TSH 40

template<int MODE>
__global__ __launch_bounds__(256, 2) void gemm_f16(
    const float* __restrict__ bias,
    float* __restrict__ Cext,
    int N, int K)
{
    extern __shared__ __half smh[];   // 3 stages x (A 128*TSH | B 128*TSH)

    int tid  = threadIdx.x;
    int lane = tid & 31, w = tid >> 5;        // 8 warps
    int g = lane >> 2, t = lane & 3;
    int wm = (w >> 2) * 64, wn = (w & 3) * 32;
    int bm = blockIdx.y * 128, bn = blockIdx.x * 128;

    int lr = tid >> 1;            // 0..127 (row)
    int lc = (tid & 1) * 16;      // 0 or 16 halves (two 16B chunks each)

    const __half* Ah = (MODE == 0) ? g_qkv16 : g_ctx;
    const __half* Bh = (MODE == 0) ? g_win16 : g_wout16;
    const __half* Ap = Ah + (size_t)(bm + lr) * K + lc;
    const __half* Bp = Bh + (size_t)(bn + lr) * K + lc;

    int a_off = (wm + (lane & 15)) * TSH * 2 + (lane >> 4) * 16;
    int b_off = (wn + (lane & 7) + 8 * (lane >> 4)) * TSH * 2 + ((lane >> 3) & 1) * 16;

    auto ISSUE = [&](int chunk) {
        __half* as = smh + (chunk % 3) * 2 * 128 * TSH;
        __half* bs = as + 128 * TSH;
        const __half* ap = Ap + chunk * BK;
        const __half* bp = Bp + chunk * BK;
        uint32_t ad = s2u(as + lr * TSH + lc);
        uint32_t bd = s2u(bs + lr * TSH + lc);
        cp16(ad,      ap);
        cp16(ad + 16, ap + 8);
        cp16(bd,      bp);
        cp16(bd + 16, bp + 8);
        CP_COMMIT();
    };

    float acc[4][4][4];
    #pragma unroll
    for (int ma = 0; ma < 4; ma++)
        #pragma unroll
        for (int na = 0; na < 4; na++)
            #pragma unroll
            for (int j = 0; j < 4; j++) acc[ma][na][j] = 0.f;

    auto COMPUTE = [&](const __half* as, const __half* bs) {
        uint32_t abase = s2u(as) + a_off;
        uint32_t bbase = s2u(bs) + b_off;
        #pragma unroll
        for (int s = 0; s < 2; s++) {
            uint32_t ko = s * 32;
            unsigned af[4][4];
            #pragma unroll
            for (int ma = 0; ma < 4; ma++)
                ldsm_x4(af[ma], abase + ma * 16 * TSH * 2 + ko);
            #pragma unroll
            for (int j = 0; j < 2; j++) {      // two n16 groups in n32
                unsigned bf[4];
                ldsm_x4(bf, bbase + j * 16 * TSH * 2 + ko);
                #pragma unroll
                for (int ma = 0; ma < 4; ma++) {
                    mma_f16(acc[ma][2 * j],     af[ma], bf[0], bf[1]);
                    mma_f16(acc[ma][2 * j + 1], af[ma], bf[2], bf[3]);
                }
            }
        }
    };

    int nch = K / BK;
    ISSUE(0);
    ISSUE(1);

    for (int i = 0; i < nch; i++) {
        if (i + 1 < nch) { CP_WAIT(1); } else { CP_WAIT(0); }
        __syncthreads();
        if (i + 2 < nch) ISSUE(i + 2);
        __half* as = smh + (i % 3) * 2 * 128 * TSH;
        COMPUTE(as, as + 128 * TSH);
    }

    #pragma unroll
    for (int ma = 0; ma < 4; ma++) {
        int r0 = bm + wm + ma * 16 + g;
        #pragma unroll
        for (int na = 0; na < 4; na++) {
            int col = bn + wn + na * 8 + 2 * t;
            float2 bv = *(const float2*)(bias + col);
            if (MODE == 0) {
                *(unsigned*)(g_proj + (size_t)r0 * N + col) =
                    packh2(acc[ma][na][0] + bv.x, acc[ma][na][1] + bv.y);
                *(unsigned*)(g_proj + (size_t)(r0 + 8) * N + col) =
                    packh2(acc[ma][na][2] + bv.x, acc[ma][na][3] + bv.y);
            } else {
                float2 o0 = { acc[ma][na][0] + bv.x, acc[ma][na][1] + bv.y };
                *(float2*)(Cext + (size_t)r0 * N + col) = o0;
                float2 o1 = { acc[ma][na][2] + bv.x, acc[ma][na][3] + bv.y };
                *(float2*)(Cext + (size_t)(r0 + 8) * N + col) = o1;
            }
        }
    }
}

// ---------------------------------------------------------------------------
// Flash attention — unchanged from Round 13 (passing, no reg cap).
// ---------------------------------------------------------------------------
#define QST 72

__global__ __launch_bounds__(128, 2) void attn_f16()
{
    extern __shared__ __half sma[];
    __half* Qs = sma;                          // [128][QST]
    __half* Kb[2] = { sma + 128 * QST, sma + 192 * QST };
    __half* Vb[2] = { sma + 256 * QST, sma + 320 * QST };

    int tid = threadIdx.x, lane = tid & 31, w = tid >> 5;
    int g = lane >> 2, t = lane & 3;
    int h = blockIdx.y, b = blockIdx.z, q0 = blockIdx.x * 128;

    const __half* base = g_proj + (size_t)b * SEQ * (3 * EMB) + h * HD;
    const float SCL = 0.125f * 1.4426950408889634f;
    const __half2 SCL2 = __float2half2_rn(SCL);

    int aoff = (w * 32 + (lane & 15)) * QST * 2 + (lane >> 4) * 16;
    int boff = ((lane & 7) + 8 * (lane >> 4)) * QST * 2 + ((lane >> 3) & 1) * 16;
    int voff = (((lane & 7) + 8 * ((lane >> 3) & 1)) * QST + 8 * (lane >> 4)) * 2;
    uint32_t qbase = s2u(Qs) + aoff;
    uint32_t kbase[2] = { s2u(Kb[0]) + boff, s2u(Kb[1]) + boff };
    uint32_t vbase[2] = { s2u(Vb[0]) + voff, s2u(Vb[1]) + voff };

    auto ISSUE_KV = [&](int kb) {
        int bi = kb & 1;
        int r = tid >> 1, cb = (tid & 1) * 32;
        const __half* ksrc = base + EMB + (size_t)(kb * 64 + r) * (3 * EMB) + cb;
        const __half* vsrc = ksrc + EMB;
        __half* kd = Kb[bi] + r * QST + cb;
        __half* vd = Vb[bi] + r * QST + cb;
        #pragma unroll
        for (int i = 0; i < 4; i++) {
            cp16(s2u(kd + i * 8), ksrc + i * 8);
            cp16(s2u(vd + i * 8), vsrc + i * 8);
        }
        CP_COMMIT();
    };

    ISSUE_KV(0);

    {
        const uint4* src = (const uint4*)(base + (size_t)(q0 + tid) * (3 * EMB));
        uint4* dst = (uint4*)(Qs + tid * QST);
        #pragma unroll
        for (int i = 0; i < 8; i++) {
            uint4 v = src[i];
            __half2* hv = (__half2*)&v;
            #pragma unroll
            for (int j = 0; j < 4; j++) hv[j] = __hmul2(hv[j], SCL2);
            dst[i] = v;
        }
    }
    __syncthreads();

    unsigned qf[4][2][4];
    #pragma unroll
    for (int ks = 0; ks < 4; ks++)
        #pragma unroll
        for (int ma = 0; ma < 2; ma++)
            ldsm_x4(qf[ks][ma], qbase + ma * 16 * QST * 2 + ks * 32);

    float m_i[2][2], l_i[2][2];
    #pragma unroll
    for (int ma = 0; ma < 2; ma++)
        #pragma unroll
        for (int hf = 0; hf < 2; hf++) { m_i[ma][hf] = -1e30f; l_i[ma][hf] = 0.f; }
    float o[2][8][4];
    #pragma unroll
    for (int ma = 0; ma < 2; ma++)
        #pragma unroll
        for (int na = 0; na < 8; na++)
            #pragma unroll
            for (int j = 0; j < 4; j++) o[ma][na][j] = 0.f;

    for (int kb = 0; kb < 16; kb++) {
        int bi = kb & 1;
        CP_WAIT(0);
        __syncthreads();
        if (kb + 1 < 16) ISSUE_KV(kb + 1);

        float sc[2][8][4];
        #pragma unroll
        for (int ma = 0; ma < 2; ma++)
            #pragma unroll
            for (int na = 0; na < 8; na++)
                #pragma unroll
                for (int j = 0; j < 4; j++) sc[ma][na][j] = 0.f;

        #pragma unroll
        for (int ks = 0; ks < 4; ks++) {
            uint32_t ko = ks * 32;
            #pragma unroll
            for (int j = 0; j < 4; j++) {
                unsigned bf[4];
                ldsm_x4(bf, kbase[bi] + j * 16 * QST * 2 + ko);
                #pragma unroll
                for (int ma = 0; ma < 2; ma++) {
                    mma_f16(sc[ma][2 * j],     qf[ks][ma], bf[0], bf[1]);
                    mma_f16(sc[ma][2 * j + 1], qf[ks][ma], bf[2], bf[3]);
                }
            }
        }

        unsigned ph[2][2][8];
        #pragma unroll
        for (int ma = 0; ma < 2; ma++) {
            #pragma unroll
            for (int hf = 0; hf < 2; hf++) {
                float rm = -1e30f;
                #pragma unroll
                for (int na = 0; na < 8; na++)
                    rm = fmaxf(rm, fmaxf(sc[ma][na][hf*2], sc[ma][na][hf*2+1]));
                rm = fmaxf(rm, __shfl_xor_sync(0xffffffffu, rm, 1));
                rm = fmaxf(rm, __shfl_xor_sync(0xffffffffu, rm, 2));
                float mn = fmaxf(m_i[ma][hf], rm);
                float al = ex2(m_i[ma][hf] - mn);
                float rs = 0.f;
                #pragma unroll
                for (int na = 0; na < 8; na++) {
                    float p0 = ex2(sc[ma][na][hf*2]   - mn);
                    float p1 = ex2(sc[ma][na][hf*2+1] - mn);
                    rs += p0 + p1;
                    ph[ma][hf][na] = packh2(p0, p1);
                    o[ma][na][hf*2]   *= al;
                    o[ma][na][hf*2+1] *= al;
                }
                rs += __shfl_xor_sync(0xffffffffu, rs, 1);
                rs += __shfl_xor_sync(0xffffffffu, rs, 2);
                l_i[ma][hf] = l_i[ma][hf] * al + rs;
                m_i[ma][hf] = mn;
            }
        }

        #pragma unroll
        for (int ks = 0; ks < 4; ks++) {
            unsigned af0[4] = { ph[0][0][2*ks], ph[0][1][2*ks],
                                ph[0][0][2*ks+1], ph[0][1][2*ks+1] };
            unsigned af1[4] = { ph[1][0][2*ks], ph[1][1][2*ks],
                                ph[1][0][2*ks+1], ph[1][1][2*ks+1] };
            #pragma unroll
            for (int j = 0; j < 4; j++) {
                unsigned bf[4];
                ldsm_x4_t(bf, vbase[bi] + (ks * 16 * QST + j * 16) * 2);
                mma_f16(o[0][2 * j],     af0, bf[0], bf[1]);
                mma_f16(o[0][2 * j + 1], af0, bf[2], bf[3]);
                mma_f16(o[1][2 * j],     af1, bf[0], bf[1]);
                mma_f16(o[1][2 * j + 1], af1, bf[2], bf[3]);
            }
        }
    }

    #pragma unroll
    for (int ma = 0; ma < 2; ma++) {
        float inv0 = 1.f / l_i[ma][0], inv1 = 1.f / l_i[ma][1];
        int row_g = b * SEQ + q0 + w * 32 + ma * 16 + g;
        __half* orow0 = g_ctx + (size_t)row_g * EMB + h * HD;
        __half* orow1 = orow0 + (size_t)8 * EMB;
        #pragma unroll
        for (int na = 0; na < 8; na++) {
            int col = na * 8 + 2 * t;
            *(unsigned*)(orow0 + col) = packh2(o[ma][na][0] * inv0, o[ma][na][1] * inv0);
            *(unsigned*)(orow1 + col) = packh2(o[ma][na][2] * inv1, o[ma][na][3] * inv1);
        }
    }
}

// ---------------------------------------------------------------------------
extern "C" void kernel_launch(void* const* d_in, const int* in_sizes, int n_in,
                              void* d_out, int out_size)
{
    (void)in_sizes; (void)n_in; (void)out_size;
    const float* qkv   = (const float*)d_in[0];
    const float* w_in  = (const float*)d_in[1];
    const float* b_in  = (const float*)d_in[2];
    const float* w_out = (const float*)d_in[3];
    const float* b_out = (const float*)d_in[4];
    float* out = (float*)d_out;

    int gemm_smem = 3 * 2 * 128 * TSH * sizeof(__half);   // 61440
    int attn_smem = 384 * QST * sizeof(__half);           // 55296
    cudaFuncSetAttribute(gemm_f16<0>, cudaFuncAttributeMaxDynamicSharedMemorySize, gemm_smem);
    cudaFuncSetAttribute(gemm_f16<1>, cudaFuncAttributeMaxDynamicSharedMemorySize, gemm_smem);
    cudaFuncSetAttribute(attn_f16, cudaFuncAttributeMaxDynamicSharedMemorySize, attn_smem);

    __half* d_qkv16, *d_win16, *d_wout16;
    cudaGetSymbolAddress((void**)&d_qkv16,  g_qkv16);
    cudaGetSymbolAddress((void**)&d_win16,  g_win16);
    cudaGetSymbolAddress((void**)&d_wout16, g_wout16);
    to_half<<<(TOK * EMB / 4 + 255) / 256, 256>>>((const float4*)qkv, (uint2*)d_qkv16, TOK * EMB / 4);
    to_half<<<(3 * EMB * EMB / 4 + 255) / 256, 256>>>((const float4*)w_in, (uint2*)d_win16, 3 * EMB * EMB / 4);
    to_half<<<(EMB * EMB / 4 + 255) / 256, 256>>>((const float4*)w_out, (uint2*)d_wout16, EMB * EMB / 4);

    dim3 g1(3 * EMB / 128, TOK / 128);
    gemm_f16<0><<<g1, 256, gemm_smem>>>(b_in, nullptr, 3 * EMB, EMB);

    dim3 g2(SEQ / 128, NH, BATCH);
    attn_f16<<<g2, 128, attn_smem>>>();

    dim3 g3(EMB / 128, TOK / 128);
    gemm_f16<1><<<g3, 256, gemm_smem>>>(b_out, out, EMB, EMB);
}

// round 16
// speedup vs baseline: 1.8515x; 1.8515x over previous
#include <cuda_runtime.h>
#include <cuda_fp16.h>
#include <math.h>
#include <stdint.h>

#define EMB   1024
#define SEQ   1024
#define BATCH 8
#define NH    16
#define HD    64
#define TOK   (BATCH*SEQ)   // 8192

// Scratch — fp16 everywhere
__device__ __half g_qkv16[(size_t)TOK * EMB];
__device__ __half g_win16[(size_t)3 * EMB * EMB];
__device__ __half g_wout16[(size_t)EMB * EMB];
__device__ __half g_proj[(size_t)TOK * 3 * EMB];
__device__ __half g_ctx[(size_t)TOK * EMB];

// ---------------------------------------------------------------------------
__device__ __forceinline__ float ex2(float x) {
    float y; asm("ex2.approx.ftz.f32 %0, %1;" : "=f"(y) : "f"(x)); return y;
}
__device__ __forceinline__ uint32_t s2u(const void* p) {
    return (uint32_t)__cvta_generic_to_shared(p);
}
__device__ __forceinline__ void mma_f16(float c[4], const unsigned a[4],
                                        unsigned b0, unsigned b1) {
    asm volatile(
        "mma.sync.aligned.m16n8k16.row.col.f32.f16.f16.f32 "
        "{%0,%1,%2,%3}, {%4,%5,%6,%7}, {%8,%9}, {%0,%1,%2,%3};"
        : "+f"(c[0]), "+f"(c[1]), "+f"(c[2]), "+f"(c[3])
        : "r"(a[0]), "r"(a[1]), "r"(a[2]), "r"(a[3]), "r"(b0), "r"(b1));
}
__device__ __forceinline__ void ldsm_x4(unsigned r[4], uint32_t addr) {
    asm volatile("ldmatrix.sync.aligned.m8n8.x4.shared.b16 {%0,%1,%2,%3}, [%4];"
        : "=r"(r[0]), "=r"(r[1]), "=r"(r[2]), "=r"(r[3]) : "r"(addr));
}
__device__ __forceinline__ void ldsm_x4_t(unsigned r[4], uint32_t addr) {
    asm volatile("ldmatrix.sync.aligned.m8n8.x4.trans.shared.b16 {%0,%1,%2,%3}, [%4];"
        : "=r"(r[0]), "=r"(r[1]), "=r"(r[2]), "=r"(r[3]) : "r"(addr));
}
__device__ __forceinline__ unsigned packh2(float a, float b) {
    __half2 h = __floats2half2_rn(a, b);
    return *(unsigned*)&h;
}
__device__ __forceinline__ void cp16(uint32_t dst, const void* src) {
    asm volatile("cp.async.cg.shared.global [%0], [%1], 16;" :: "r"(dst), "l"(src));
}
#define CP_COMMIT() asm volatile("cp.async.commit_group;")
#define CP_WAIT(n)  asm volatile("cp.async.wait_group %0;" :: "n"(n))

// ---------------------------------------------------------------------------
__global__ __launch_bounds__(256) void to_half(const float4* __restrict__ src,
                                               uint2* __restrict__ dst, int n4)
{
    int i = blockIdx.x * blockDim.x + threadIdx.x;
    if (i < n4) {
        float4 v = src[i];
        uint2 o = { packh2(v.x, v.y), packh2(v.z, v.w) };
        dst[i] = o;
    }
}

// ---------------------------------------------------------------------------
// GEMM: CTA 128x128, 4 warps (2x2), warp tile 64x64, BK=32. (R13 config)
// 4-stage cp.async ring, 3 chunks of prefetch lead (CP_WAIT(2) steady state).
// ---------------------------------------------------------------------------
#define BK  32
#define TSH 40

template<int MODE>
__global__ __launch_bounds__(128, 2) void gemm_f16(
    const float* __restrict__ bias,
    float* __restrict__ Cext,
    int N, int K)
{
    extern __shared__ __half smh[];   // 4 stages x (A 128*TSH | B 128*TSH)

    int tid  = threadIdx.x;
    int lane = tid & 31, w = tid >> 5;
    int g = lane >> 2, t = lane & 3;
    int wm = (w >> 1) * 64, wn = (w & 1) * 64;
    int bm = blockIdx.y * 128, bn = blockIdx.x * 128;

    int lr = tid >> 2;        // 0..31
    int lc = (tid & 3) * 8;   // 0,8,16,24 halves (16B)

    const __half* Ah = (MODE == 0) ? g_qkv16 : g_ctx;
    const __half* Bh = (MODE == 0) ? g_win16 : g_wout16;
    const __half* Ap = Ah + (size_t)(bm + lr) * K + lc;
    const __half* Bp = Bh + (size_t)(bn + lr) * K + lc;

    int a_off = (wm + (lane & 15)) * TSH * 2 + (lane >> 4) * 16;
    int b_off = (wn + (lane & 7) + 8 * (lane >> 4)) * TSH * 2 + ((lane >> 3) & 1) * 16;

    auto ISSUE = [&](int chunk) {
        __half* as = smh + (chunk & 3) * 2 * 128 * TSH;
        __half* bs = as + 128 * TSH;
        const __half* ap = Ap + chunk * BK;
        const __half* bp = Bp + chunk * BK;
        #pragma unroll
        for (int i = 0; i < 4; i++) {
            int r = lr + 32 * i;
            cp16(s2u(as + r * TSH + lc), ap + (size_t)(32 * i) * K);
            cp16(s2u(bs + r * TSH + lc), bp + (size_t)(32 * i) * K);
        }
        CP_COMMIT();
    };

    float acc[4][8][4];
    #pragma unroll
    for (int ma = 0; ma < 4; ma++)
        #pragma unroll
        for (int na = 0; na < 8; na++)
            #pragma unroll
            for (int j = 0; j < 4; j++) acc[ma][na][j] = 0.f;

    auto COMPUTE = [&](const __half* as, const __half* bs) {
        uint32_t abase = s2u(as) + a_off;
        uint32_t bbase = s2u(bs) + b_off;
        #pragma unroll
        for (int s = 0; s < 2; s++) {
            uint32_t ko = s * 32;
            unsigned af[4][4];
            #pragma unroll
            for (int ma = 0; ma < 4; ma++)
                ldsm_x4(af[ma], abase + ma * 16 * TSH * 2 + ko);
            #pragma unroll
            for (int j = 0; j < 4; j++) {
                unsigned bf[4];
                ldsm_x4(bf, bbase + j * 16 * TSH * 2 + ko);
                #pragma unroll
                for (int ma = 0; ma < 4; ma++) {
                    mma_f16(acc[ma][2 * j],     af[ma], bf[0], bf[1]);
                    mma_f16(acc[ma][2 * j + 1], af[ma], bf[2], bf[3]);
                }
            }
        }
    };

    int nch = K / BK;
    ISSUE(0);
    ISSUE(1);
    ISSUE(2);

    for (int i = 0; i < nch; i++) {
        // need group i complete; up to 2 newer groups may stay outstanding
        if (i + 2 < nch)      { CP_WAIT(2); }
        else if (i + 1 < nch) { CP_WAIT(1); }
        else                  { CP_WAIT(0); }
        __syncthreads();                 // chunk i visible; compute(i-1) done everywhere
        if (i + 3 < nch) ISSUE(i + 3);   // stage (i+3)&3 = (i-1)&3, safe after sync
        __half* as = smh + (i & 3) * 2 * 128 * TSH;
        COMPUTE(as, as + 128 * TSH);
    }

    #pragma unroll
    for (int ma = 0; ma < 4; ma++) {
        int r0 = bm + wm + ma * 16 + g;
        #pragma unroll
        for (int na = 0; na < 8; na++) {
            int col = bn + wn + na * 8 + 2 * t;
            float2 bv = *(const float2*)(bias + col);
            if (MODE == 0) {
                *(unsigned*)(g_proj + (size_t)r0 * N + col) =
                    packh2(acc[ma][na][0] + bv.x, acc[ma][na][1] + bv.y);
                *(unsigned*)(g_proj + (size_t)(r0 + 8) * N + col) =
                    packh2(acc[ma][na][2] + bv.x, acc[ma][na][3] + bv.y);
            } else {
                float2 o0 = { acc[ma][na][0] + bv.x, acc[ma][na][1] + bv.y };
                *(float2*)(Cext + (size_t)r0 * N + col) = o0;
                float2 o1 = { acc[ma][na][2] + bv.x, acc[ma][na][3] + bv.y };
                *(float2*)(Cext + (size_t)(r0 + 8) * N + col) = o1;
            }
        }
    }
}

// ---------------------------------------------------------------------------
// Flash attention — unchanged from Round 13 (passing).
// ---------------------------------------------------------------------------
#define QST 72

__global__ __launch_bounds__(128, 2) void attn_f16()
{
    extern __shared__ __half sma[];
    __half* Qs = sma;                          // [128][QST]
    __half* Kb[2] = { sma + 128 * QST, sma + 192 * QST };
    __half* Vb[2] = { sma + 256 * QST, sma + 320 * QST };

    int tid = threadIdx.x, lane = tid & 31, w = tid >> 5;
    int g = lane >> 2, t = lane & 3;
    int h = blockIdx.y, b = blockIdx.z, q0 = blockIdx.x * 128;

    const __half* base = g_proj + (size_t)b * SEQ * (3 * EMB) + h * HD;
    const float SCL = 0.125f * 1.4426950408889634f;
    const __half2 SCL2 = __float2half2_rn(SCL);

    int aoff = (w * 32 + (lane & 15)) * QST * 2 + (lane >> 4) * 16;
    int boff = ((lane & 7) + 8 * (lane >> 4)) * QST * 2 + ((lane >> 3) & 1) * 16;
    int voff = (((lane & 7) + 8 * ((lane >> 3) & 1)) * QST + 8 * (lane >> 4)) * 2;
    uint32_t qbase = s2u(Qs) + aoff;
    uint32_t kbase[2] = { s2u(Kb[0]) + boff, s2u(Kb[1]) + boff };
    uint32_t vbase[2] = { s2u(Vb[0]) + voff, s2u(Vb[1]) + voff };

    auto ISSUE_KV = [&](int kb) {
        int bi = kb & 1;
        int r = tid >> 1, cb = (tid & 1) * 32;
        const __half* ksrc = base + EMB + (size_t)(kb * 64 + r) * (3 * EMB) + cb;
        const __half* vsrc = ksrc + EMB;
        __half* kd = Kb[bi] + r * QST + cb;
        __half* vd = Vb[bi] + r * QST + cb;
        #pragma unroll
        for (int i = 0; i < 4; i++) {
            cp16(s2u(kd + i * 8), ksrc + i * 8);
            cp16(s2u(vd + i * 8), vsrc + i * 8);
        }
        CP_COMMIT();
    };

    ISSUE_KV(0);

    {
        const uint4* src = (const uint4*)(base + (size_t)(q0 + tid) * (3 * EMB));
        uint4* dst = (uint4*)(Qs + tid * QST);
        #pragma unroll
        for (int i = 0; i < 8; i++) {
            uint4 v = src[i];
            __half2* hv = (__half2*)&v;
            #pragma unroll
            for (int j = 0; j < 4; j++) hv[j] = __hmul2(hv[j], SCL2);
            dst[i] = v;
        }
    }
    __syncthreads();

    unsigned qf[4][2][4];
    #pragma unroll
    for (int ks = 0; ks < 4; ks++)
        #pragma unroll
        for (int ma = 0; ma < 2; ma++)
            ldsm_x4(qf[ks][ma], qbase + ma * 16 * QST * 2 + ks * 32);

    float m_i[2][2], l_i[2][2];
    #pragma unroll
    for (int ma = 0; ma < 2; ma++)
        #pragma unroll
        for (int hf = 0; hf < 2; hf++) { m_i[ma][hf] = -1e30f; l_i[ma][hf] = 0.f; }
    float o[2][8][4];
    #pragma unroll
    for (int ma = 0; ma < 2; ma++)
        #pragma unroll
        for (int na = 0; na < 8; na++)
            #pragma unroll
            for (int j = 0; j < 4; j++) o[ma][na][j] = 0.f;

    for (int kb = 0; kb < 16; kb++) {
        int bi = kb & 1;
        CP_WAIT(0);
        __syncthreads();
        if (kb + 1 < 16) ISSUE_KV(kb + 1);

        float sc[2][8][4];
        #pragma unroll
        for (int ma = 0; ma < 2; ma++)
            #pragma unroll
            for (int na = 0; na < 8; na++)
                #pragma unroll
                for (int j = 0; j < 4; j++) sc[ma][na][j] = 0.f;

        #pragma unroll
        for (int ks = 0; ks < 4; ks++) {
            uint32_t ko = ks * 32;
            #pragma unroll
            for (int j = 0; j < 4; j++) {
                unsigned bf[4];
                ldsm_x4(bf, kbase[bi] + j * 16 * QST * 2 + ko);
                #pragma unroll
                for (int ma = 0; ma < 2; ma++) {
                    mma_f16(sc[ma][2 * j],     qf[ks][ma], bf[0], bf[1]);
                    mma_f16(sc[ma][2 * j + 1], qf[ks][ma], bf[2], bf[3]);
                }
            }
        }

        unsigned ph[2][2][8];
        #pragma unroll
        for (int ma = 0; ma < 2; ma++) {
            #pragma unroll
            for (int hf = 0; hf < 2; hf++) {
                float rm = -1e30f;
                #pragma unroll
                for (int na = 0; na < 8; na++)
                    rm = fmaxf(rm, fmaxf(sc[ma][na][hf*2], sc[ma][na][hf*2+1]));
                rm = fmaxf(rm, __shfl_xor_sync(0xffffffffu, rm, 1));
                rm = fmaxf(rm, __shfl_xor_sync(0xffffffffu, rm, 2));
                float mn = fmaxf(m_i[ma][hf], rm);
                float al = ex2(m_i[ma][hf] - mn);
                float rs = 0.f;
                #pragma unroll
                for (int na = 0; na < 8; na++) {
                    float p0 = ex2(sc[ma][na][hf*2]   - mn);
                    float p1 = ex2(sc[ma][na][hf*2+1] - mn);
                    rs += p0 + p1;
                    ph[ma][hf][na] = packh2(p0, p1);
                    o[ma][na][hf*2]   *= al;
                    o[ma][na][hf*2+1] *= al;
                }
                rs += __shfl_xor_sync(0xffffffffu, rs, 1);
                rs += __shfl_xor_sync(0xffffffffu, rs, 2);
                l_i[ma][hf] = l_i[ma][hf] * al + rs;
                m_i[ma][hf] = mn;
            }
        }

        #pragma unroll
        for (int ks = 0; ks < 4; ks++) {
            unsigned af0[4] = { ph[0][0][2*ks], ph[0][1][2*ks],
                                ph[0][0][2*ks+1], ph[0][1][2*ks+1] };
            unsigned af1[4] = { ph[1][0][2*ks], ph[1][1][2*ks],
                                ph[1][0][2*ks+1], ph[1][1][2*ks+1] };
            #pragma unroll
            for (int j = 0; j < 4; j++) {
                unsigned bf[4];
                ldsm_x4_t(bf, vbase[bi] + (ks * 16 * QST + j * 16) * 2);
                mma_f16(o[0][2 * j],     af0, bf[0], bf[1]);
                mma_f16(o[0][2 * j + 1], af0, bf[2], bf[3]);
                mma_f16(o[1][2 * j],     af1, bf[0], bf[1]);
                mma_f16(o[1][2 * j + 1], af1, bf[2], bf[3]);
            }
        }
    }

    #pragma unroll
    for (int ma = 0; ma < 2; ma++) {
        float inv0 = 1.f / l_i[ma][0], inv1 = 1.f / l_i[ma][1];
        int row_g = b * SEQ + q0 + w * 32 + ma * 16 + g;
        __half* orow0 = g_ctx + (size_t)row_g * EMB + h * HD;
        __half* orow1 = orow0 + (size_t)8 * EMB;
        #pragma unroll
        for (int na = 0; na < 8; na++) {
            int col = na * 8 + 2 * t;
            *(unsigned*)(orow0 + col) = packh2(o[ma][na][0] * inv0, o[ma][na][1] * inv0);
            *(unsigned*)(orow1 + col) = packh2(o[ma][na][2] * inv1, o[ma][na][3] * inv1);
        }
    }
}

// ---------------------------------------------------------------------------
extern "C" void kernel_launch(void* const* d_in, const int* in_sizes, int n_in,
                              void* d_out, int out_size)
{
    (void)in_sizes; (void)n_in; (void)out_size;
    const float* qkv   = (const float*)d_in[0];
    const float* w_in  = (const float*)d_in[1];
    const float* b_in  = (const float*)d_in[2];
    const float* w_out = (const float*)d_in[3];
    const float* b_out = (const float*)d_in[4];
    float* out = (float*)d_out;

    int gemm_smem = 4 * 2 * 128 * TSH * sizeof(__half);   // 81920
    int attn_smem = 384 * QST * sizeof(__half);           // 55296
    cudaFuncSetAttribute(gemm_f16<0>, cudaFuncAttributeMaxDynamicSharedMemorySize, gemm_smem);
    cudaFuncSetAttribute(gemm_f16<1>, cudaFuncAttributeMaxDynamicSharedMemorySize, gemm_smem);
    cudaFuncSetAttribute(attn_f16, cudaFuncAttributeMaxDynamicSharedMemorySize, attn_smem);

    __half* d_qkv16, *d_win16, *d_wout16;
    cudaGetSymbolAddress((void**)&d_qkv16,  g_qkv16);
    cudaGetSymbolAddress((void**)&d_win16,  g_win16);
    cudaGetSymbolAddress((void**)&d_wout16, g_wout16);
    to_half<<<(TOK * EMB / 4 + 255) / 256, 256>>>((const float4*)qkv, (uint2*)d_qkv16, TOK * EMB / 4);
    to_half<<<(3 * EMB * EMB / 4 + 255) / 256, 256>>>((const float4*)w_in, (uint2*)d_win16, 3 * EMB * EMB / 4);
    to_half<<<(EMB * EMB / 4 + 255) / 256, 256>>>((const float4*)w_out, (uint2*)d_wout16, EMB * EMB / 4);

    dim3 g1(3 * EMB / 128, TOK / 128);
    gemm_f16<0><<<g1, 128, gemm_smem>>>(b_in, nullptr, 3 * EMB, EMB);

    dim3 g2(SEQ / 128, NH, BATCH);
    attn_f16<<<g2, 128, attn_smem>>>();

    dim3 g3(EMB / 128, TOK / 128);
    gemm_f16<1><<<g3, 128, gemm_smem>>>(b_out, out, EMB, EMB);
}